// round 1
// baseline (speedup 1.0000x reference)
#include <cuda_runtime.h>
#include <math.h>

// CustomCrossEntropyLoss: ce = -mean(log(y[b, argmax(target_b)] + 1e-8))
//                         pt = sum_{b,c} wtab[popc(t_b ^ c)] * y[b,c] / (B*N)
//                         out = ce + pt   (scalar float)
// N = 1024 (dim = 10 bits), wtab[0]=0, wtab[p]=6^p.

#define NCLS   1024
#define BLOCKS 2048
#define TPB    256
#define WPB    (TPB / 32)

__device__ double g_part_ce[BLOCKS];
__device__ double g_part_pt[BLOCKS];

__global__ __launch_bounds__(TPB)
void ce_pt_kernel(const float* __restrict__ y, const float* __restrict__ tgt, int B) {
    __shared__ float  wtab[16];
    __shared__ double s_ce[WPB], s_pt[WPB];

    const int tid  = threadIdx.x;
    const int lane = tid & 31;
    const int wid  = tid >> 5;

    if (tid < 11) {
        float w = 1.0f;
        for (int i = 0; i < tid; i++) w *= 6.0f;   // exact: 6^10 < 2^26
        wtab[tid] = (tid == 0) ? 0.0f : w;
    }
    __syncthreads();

    const int gw = blockIdx.x * WPB + wid;
    const int nw = gridDim.x * WPB;

    double acc_ce = 0.0, acc_pt = 0.0;

    for (int r = gw; r < B; r += nw) {
        // ---- pass 1: argmax of target row (first-max tie-break, like jnp.argmax) ----
        const float4* trow = (const float4*)(tgt + (size_t)r * NCLS);
        float bv = -1.0f;
        int   bi = 0;
        #pragma unroll
        for (int it = 0; it < 8; it++) {
            float4 v = trow[it * 32 + lane];
            int c = (it * 32 + lane) * 4;
            if (v.x > bv) { bv = v.x; bi = c;     }
            if (v.y > bv) { bv = v.y; bi = c + 1; }
            if (v.z > bv) { bv = v.z; bi = c + 2; }
            if (v.w > bv) { bv = v.w; bi = c + 3; }
        }
        #pragma unroll
        for (int off = 16; off; off >>= 1) {
            float ov = __shfl_xor_sync(0xFFFFFFFFu, bv, off);
            int   oi = __shfl_xor_sync(0xFFFFFFFFu, bi, off);
            if (ov > bv || (ov == bv && oi < bi)) { bv = ov; bi = oi; }
        }
        const int t = bi;   // identical in all lanes

        // ---- pass 2: weighted sum over y row ----
        const float4* yrow = (const float4*)(y + (size_t)r * NCLS);
        float pt = 0.0f;
        #pragma unroll
        for (int it = 0; it < 8; it++) {
            float4 v = yrow[it * 32 + lane];
            int c = (it * 32 + lane) * 4;
            pt = fmaf(wtab[__popc(t ^  c     )], v.x, pt);
            pt = fmaf(wtab[__popc(t ^ (c + 1))], v.y, pt);
            pt = fmaf(wtab[__popc(t ^ (c + 2))], v.z, pt);
            pt = fmaf(wtab[__popc(t ^ (c + 3))], v.w, pt);
        }
        #pragma unroll
        for (int off = 16; off; off >>= 1)
            pt += __shfl_xor_sync(0xFFFFFFFFu, pt, off);

        if (lane == 0) {
            acc_pt += (double)pt;
            float yt = y[(size_t)r * NCLS + t];   // line already resident in L1/L2
            acc_ce += (double)logf(yt + 1e-8f);
        }
    }

    if (lane == 0) { s_ce[wid] = acc_ce; s_pt[wid] = acc_pt; }
    __syncthreads();
    if (tid == 0) {
        double c = 0.0, p = 0.0;
        #pragma unroll
        for (int i = 0; i < WPB; i++) { c += s_ce[i]; p += s_pt[i]; }
        g_part_ce[blockIdx.x] = c;
        g_part_pt[blockIdx.x] = p;
    }
}

__global__ __launch_bounds__(1024)
void finish_kernel(float* __restrict__ out, int B) {
    __shared__ double s_ce[32], s_pt[32];
    const int tid = threadIdx.x, lane = tid & 31, wid = tid >> 5;

    double c = 0.0, p = 0.0;
    for (int i = tid; i < BLOCKS; i += blockDim.x) {
        c += g_part_ce[i];
        p += g_part_pt[i];
    }
    #pragma unroll
    for (int off = 16; off; off >>= 1) {
        c += __shfl_xor_sync(0xFFFFFFFFu, c, off);
        p += __shfl_xor_sync(0xFFFFFFFFu, p, off);
    }
    if (lane == 0) { s_ce[wid] = c; s_pt[wid] = p; }
    __syncthreads();
    if (tid == 0) {
        double C = 0.0, P = 0.0;
        for (int i = 0; i < (int)(blockDim.x / 32); i++) { C += s_ce[i]; P += s_pt[i]; }
        out[0] = (float)(-C / (double)B + P / ((double)B * (double)NCLS));
    }
}

extern "C" void kernel_launch(void* const* d_in, const int* in_sizes, int n_in,
                              void* d_out, int out_size) {
    const float* y_true = (const float*)d_in[0];
    const float* target = (const float*)d_in[1];
    const int B = in_sizes[0] / NCLS;

    ce_pt_kernel<<<BLOCKS, TPB>>>(y_true, target, B);
    finish_kernel<<<1, 1024>>>((float*)d_out, B);
}

// round 2
// speedup vs baseline: 1.1502x; 1.1502x over previous
#include <cuda_runtime.h>
#include <math.h>

// out = -mean_b log(y[b, argmax(target_b)] + 1e-8)
//       + sum_{b,c} wtab[popc(t_b ^ c)] * y[b,c] / (B*N)
// N = 1024 (10 bits), wtab[0]=0, wtab[p]=6^p (exact in fp32).

#define NCLS   1024
#define BLOCKS 2048
#define TPB    256
#define WPB    (TPB / 32)

__device__ double   g_ce = 0.0;
__device__ double   g_pt = 0.0;
__device__ unsigned g_count = 0;

__global__ __launch_bounds__(TPB)
void ce_pt_kernel(const float* __restrict__ y, const float* __restrict__ tgt,
                  float* __restrict__ out, int B) {
    __shared__ float  wtab[16];
    __shared__ double s_ce[WPB], s_pt[WPB];

    const int tid  = threadIdx.x;
    const int lane = tid & 31;
    const int wid  = tid >> 5;

    if (tid < 11) {
        float w = 1.0f;
        for (int i = 0; i < tid; i++) w *= 6.0f;   // exact: 6^10 < 2^26
        wtab[tid] = (tid == 0) ? 0.0f : w;
    }
    __syncthreads();

    const int gw = blockIdx.x * WPB + wid;
    const int nw = gridDim.x * WPB;

    float  acc_pt = 0.0f;   // per-lane partial across rows
    double acc_ce = 0.0;    // only the lane owning t contributes per row

    for (int r = gw; r < B; r += nw) {
        const float4* trow = (const float4*)(tgt + (size_t)r * NCLS);
        const float4* yrow = (const float4*)(y   + (size_t)r * NCLS);

        // ---- preload both rows: 16 independent LDG.128 per lane ----
        float4 tv[8], yv[8];
        #pragma unroll
        for (int it = 0; it < 8; it++) {
            tv[it] = trow[it * 32 + lane];
            yv[it] = yrow[it * 32 + lane];
        }

        // ---- argmax over target (first-max tie-break) ----
        float bv = -1.0f;
        int   bi = 0;
        #pragma unroll
        for (int it = 0; it < 8; it++) {
            int c = (it * 32 + lane) * 4;
            if (tv[it].x > bv) { bv = tv[it].x; bi = c;     }
            if (tv[it].y > bv) { bv = tv[it].y; bi = c + 1; }
            if (tv[it].z > bv) { bv = tv[it].z; bi = c + 2; }
            if (tv[it].w > bv) { bv = tv[it].w; bi = c + 3; }
        }
        #pragma unroll
        for (int off = 16; off; off >>= 1) {
            float ov = __shfl_xor_sync(0xFFFFFFFFu, bv, off);
            int   oi = __shfl_xor_sync(0xFFFFFFFFu, bi, off);
            if (ov > bv || (ov == bv && oi < bi)) { bv = ov; bi = oi; }
        }
        const int t = bi;   // identical in all lanes

        // ---- weighted sum from registers ----
        float pt = 0.0f;
        #pragma unroll
        for (int it = 0; it < 8; it++) {
            int c = (it * 32 + lane) * 4;
            pt = fmaf(wtab[__popc(t ^  c     )], yv[it].x, pt);
            pt = fmaf(wtab[__popc(t ^ (c + 1))], yv[it].y, pt);
            pt = fmaf(wtab[__popc(t ^ (c + 2))], yv[it].z, pt);
            pt = fmaf(wtab[__popc(t ^ (c + 3))], yv[it].w, pt);
        }
        acc_pt += pt;

        // ---- CE term: extract y[t] from the registers of the owning lane ----
        if (lane == ((t >> 2) & 31)) {
            const int itq = t >> 7;
            const int cq  = t & 3;
            float4 v = yv[0];
            #pragma unroll
            for (int it = 1; it < 8; it++) if (it == itq) v = yv[it];
            float yt = (cq == 0) ? v.x : (cq == 1) ? v.y : (cq == 2) ? v.z : v.w;
            acc_ce += (double)logf(yt + 1e-8f);
        }
    }

    // ---- warp reduce (once, after all rows) ----
    double dpt = (double)acc_pt;
    #pragma unroll
    for (int off = 16; off; off >>= 1) {
        dpt    += __shfl_xor_sync(0xFFFFFFFFu, dpt,    off);
        acc_ce += __shfl_xor_sync(0xFFFFFFFFu, acc_ce, off);
    }
    if (lane == 0) { s_ce[wid] = acc_ce; s_pt[wid] = dpt; }
    __syncthreads();

    // ---- block reduce + fenced last-block finish ----
    if (tid == 0) {
        double bce = 0.0, bpt = 0.0;
        #pragma unroll
        for (int i = 0; i < WPB; i++) { bce += s_ce[i]; bpt += s_pt[i]; }
        atomicAdd(&g_ce, bce);
        atomicAdd(&g_pt, bpt);
        __threadfence();
        unsigned old = atomicAdd(&g_count, 1u);
        if (old == gridDim.x - 1) {
            // read through L2 (atomics bypass L1; plain LDG could hit stale L1)
            double CE = atomicAdd(&g_ce, 0.0);
            double PT = atomicAdd(&g_pt, 0.0);
            out[0] = (float)(-CE / (double)B + PT / ((double)B * (double)NCLS));
            // reset for next graph replay (no other block touches these now)
            g_ce = 0.0;
            g_pt = 0.0;
            g_count = 0u;
        }
    }
}

extern "C" void kernel_launch(void* const* d_in, const int* in_sizes, int n_in,
                              void* d_out, int out_size) {
    const float* y_true = (const float*)d_in[0];
    const float* target = (const float*)d_in[1];
    const int B = in_sizes[0] / NCLS;

    ce_pt_kernel<<<BLOCKS, TPB>>>(y_true, target, (float*)d_out, B);
}